// round 1
// baseline (speedup 1.0000x reference)
#include <cuda_runtime.h>
#include <math.h>

#define N_NODES 100000
#define E_EDGES 800000
#define G_GRAPHS 512
#define HID 32
#define D_CUT 5.0f

// ---------------- scratch (static, no allocation) ----------------
__device__ float g_ss[G_GRAPHS * 64];        // time MLP output per graph
__device__ float g_xm[N_NODES * 32];         // modulated x
__device__ float g_a[N_NODES * 32];          // x @ msg_w1[:32] + msg_b1
__device__ float g_b[N_NODES * 32];          // x @ msg_w1[32:]
__device__ float g_gate[N_NODES * 32];       // sigmoid(x @ gate_w + gate_b)
__device__ float g_macc[N_NODES * 32];       // segment_sum(m_ij) by j
__device__ float g_pacc[N_NODES * 4];        // pos sums (3) + count (1)

__device__ __forceinline__ float siluf(float v) { return v / (1.0f + __expf(-v)); }
__device__ __forceinline__ float sigmf(float v) { return 1.0f / (1.0f + __expf(-v)); }

// ---------------- K1: time MLP (G x 128 -> G x 64) ----------------
__global__ void k_time(const float* __restrict__ time,
                       const float* __restrict__ w1, const float* __restrict__ b1,
                       const float* __restrict__ w2, const float* __restrict__ b2) {
    int g = blockIdx.x;
    int t = threadIdx.x; // 64 threads
    __shared__ float trow[128];
    __shared__ float hid[64];
    trow[t]      = time[g * 128 + t];
    trow[t + 64] = time[g * 128 + 64 + t];
    __syncthreads();
    float acc = b1[t];
    #pragma unroll 8
    for (int k = 0; k < 128; k++) acc += trow[k] * w1[k * 64 + t];
    hid[t] = siluf(acc);
    __syncthreads();
    float acc2 = b2[t];
    #pragma unroll 8
    for (int k = 0; k < 64; k++) acc2 += hid[k] * w2[k * 64 + t];
    g_ss[g * 64 + t] = acc2;
}

// ---------------- K2: per-node precompute + accumulator zeroing ----------------
// 256 threads = 8 nodes x 32 lanes (lane = channel)
__global__ void k_node(const float* __restrict__ x, const int* __restrict__ batch,
                       const float* __restrict__ msg_w1, const float* __restrict__ msg_b1,
                       const float* __restrict__ gate_w, const float* __restrict__ gate_b) {
    __shared__ float sW1[64 * 32];
    __shared__ float sWg[32 * 32];
    __shared__ float sxm[8][32];
    int tid = threadIdx.x;
    for (int k = tid; k < 2048; k += 256) sW1[k] = msg_w1[k];
    for (int k = tid; k < 1024; k += 256) sWg[k] = gate_w[k];

    int warp = tid >> 5;
    int lane = tid & 31;
    int n = blockIdx.x * 8 + warp;

    int bn = batch[n];
    float scale = g_ss[bn * 64 + lane];
    float shift = g_ss[bn * 64 + 32 + lane];
    float xv = x[n * 32 + lane];
    float xm = siluf(xv * (1.0f + scale) + shift);
    sxm[warp][lane] = xm;
    g_xm[n * 32 + lane] = xm;
    __syncthreads();

    float a = msg_b1[lane];
    float b = 0.0f;
    float ga = gate_b[lane];
    #pragma unroll
    for (int k = 0; k < 32; k++) {
        float v = sxm[warp][k];
        a  += v * sW1[k * 32 + lane];
        b  += v * sW1[(32 + k) * 32 + lane];
        ga += v * sWg[k * 32 + lane];
    }
    g_a[n * 32 + lane] = a;
    g_b[n * 32 + lane] = b;
    g_gate[n * 32 + lane] = sigmf(ga);

    g_macc[n * 32 + lane] = 0.0f;
    if (lane < 4) g_pacc[n * 4 + lane] = 0.0f;
}

// ---------------- K3: edge kernel ----------------
// 256 threads = 64 edges x 4 lanes; each lane owns 8 channels.
// Matvec: input vector distributed 8-per-lane, broadcast via shfl(width=4),
// weights streamed from smem as float4 pairs (broadcast pattern, conflict-free).
#define MV32(accv, inv, W, c0)                                                   \
    do {                                                                         \
        _Pragma("unroll")                                                        \
        for (int kk = 0; kk < 32; kk++) {                                        \
            float v = __shfl_sync(0xffffffffu, inv[kk & 7], kk >> 3, 4);         \
            const float4* wp = (const float4*)&W[kk * 32 + c0];                  \
            float4 w0 = wp[0];                                                   \
            float4 w1 = wp[1];                                                   \
            accv[0] += v * w0.x; accv[1] += v * w0.y;                            \
            accv[2] += v * w0.z; accv[3] += v * w0.w;                            \
            accv[4] += v * w1.x; accv[5] += v * w1.y;                            \
            accv[6] += v * w1.z; accv[7] += v * w1.w;                            \
        }                                                                        \
    } while (0)

__global__ void __launch_bounds__(256) k_edge(
        const int* __restrict__ ei, const float* __restrict__ pos,
        const float* __restrict__ means, const float* __restrict__ betas,
        const float* __restrict__ w_dist,
        const float* __restrict__ msg_w2, const float* __restrict__ msg_b2,
        const float* __restrict__ coord_w1, const float* __restrict__ coord_b1,
        const float* __restrict__ coord_w2, const float* __restrict__ coord_b2) {
    __shared__ __align__(16) float sWd[1024];
    __shared__ __align__(16) float sW2[1024];
    __shared__ __align__(16) float sC1[1024];
    __shared__ float sC2[32], sB2[32], sCB1[32], sMu[32], sBeta[32];
    __shared__ float sCB2;

    int tid = threadIdx.x;
    for (int k = tid; k < 1024; k += 256) {
        sWd[k] = w_dist[k];
        sW2[k] = msg_w2[k];
        sC1[k] = coord_w1[k];
    }
    if (tid < 32) {
        sC2[tid]  = coord_w2[tid];
        sB2[tid]  = msg_b2[tid];
        sCB1[tid] = coord_b1[tid];
        sMu[tid]  = means[tid];
        sBeta[tid] = betas[tid];
    }
    if (tid == 0) sCB2 = coord_b2[0];
    __syncthreads();

    int sub = tid & 3;
    int c0 = sub * 8;
    int e = blockIdx.x * 64 + (tid >> 2); // E = 800000 = 12500*64 exactly

    int i = ei[e];
    int j = ei[E_EDGES + e];

    // gathers (L2-resident)
    const float4* ap = (const float4*)&g_a[i * 32 + c0];
    const float4* bp = (const float4*)&g_b[j * 32 + c0];
    const float4* gp = (const float4*)&g_gate[j * 32 + c0];
    float4 a0 = ap[0], a1 = ap[1];
    float4 b0 = bp[0], b1v = bp[1];
    float4 gq0 = gp[0], gq1 = gp[1];

    float dx = pos[i * 3 + 0] - pos[j * 3 + 0];
    float dy = pos[i * 3 + 1] - pos[j * 3 + 1];
    float dz = pos[i * 3 + 2] - pos[j * 3 + 2];
    float dist = sqrtf(dx * dx + dy * dy + dz * dz);

    float dcl = fminf(dist, D_CUT);
    float cutoff = 0.5f * (__cosf(dcl * (3.14159265358979f / D_CUT)) + 1.0f);
    float ed = __expf(-dist);

    // rbf input (cutoff * rbf)
    float ind[8];
    #pragma unroll
    for (int u = 0; u < 8; u++) {
        float t = ed - sMu[c0 + u];
        ind[u] = cutoff * __expf(-sBeta[c0 + u] * t * t);
    }
    float de[8] = {0, 0, 0, 0, 0, 0, 0, 0};
    MV32(de, ind, sWd, c0);

    // h = silu(a_i + b_j)   (msg_b1 folded into a)
    float h[8];
    h[0] = siluf(a0.x + b0.x);  h[1] = siluf(a0.y + b0.y);
    h[2] = siluf(a0.z + b0.z);  h[3] = siluf(a0.w + b0.w);
    h[4] = siluf(a1.x + b1v.x); h[5] = siluf(a1.y + b1v.y);
    h[6] = siluf(a1.z + b1v.z); h[7] = siluf(a1.w + b1v.w);

    float mm[8];
    #pragma unroll
    for (int u = 0; u < 8; u++) mm[u] = sB2[c0 + u];
    MV32(mm, h, sW2, c0);

    float gv[8] = {gq0.x, gq0.y, gq0.z, gq0.w, gq1.x, gq1.y, gq1.z, gq1.w};
    float m[8];
    #pragma unroll
    for (int u = 0; u < 8; u++) m[u] = siluf(mm[u]) * de[u] * gv[u];

    float st[8];
    #pragma unroll
    for (int u = 0; u < 8; u++) st[u] = sCB1[c0 + u];
    MV32(st, m, sC1, c0);

    float sp = 0.0f;
    #pragma unroll
    for (int u = 0; u < 8; u++) sp += siluf(st[u]) * sC2[c0 + u];
    sp += __shfl_xor_sync(0xffffffffu, sp, 1);
    sp += __shfl_xor_sync(0xffffffffu, sp, 2);
    float s = sp + sCB2;

    // scatter m_ij into m_acc[j]
    float* macc = &g_macc[j * 32 + c0];
    #pragma unroll
    for (int u = 0; u < 8; u++) atomicAdd(macc + u, m[u]);

    // pos update: lanes 0..2 carry components, lane 3 carries the count
    float pd = (sub == 0) ? dx : (sub == 1) ? dy : dz;
    float val = (sub == 3) ? 1.0f : pd * s;
    atomicAdd(&g_pacc[j * 4 + sub], val);
}

// ---------------- K4: combine + outputs ----------------
// 256 threads = 8 nodes x 32 lanes
__global__ void k_final(const float* __restrict__ pos,
                        const float* __restrict__ comb_w1, const float* __restrict__ cb1,
                        const float* __restrict__ comb_w2, const float* __restrict__ cb2,
                        float* __restrict__ outx, float* __restrict__ outp) {
    __shared__ float sW1[64 * 32];
    __shared__ float sW2[32 * 32];
    __shared__ float scat[8][64];
    __shared__ float sh[8][32];
    int tid = threadIdx.x;
    for (int k = tid; k < 2048; k += 256) sW1[k] = comb_w1[k];
    for (int k = tid; k < 1024; k += 256) sW2[k] = comb_w2[k];

    int warp = tid >> 5;
    int lane = tid & 31;
    int n = blockIdx.x * 8 + warp;

    float xm = g_xm[n * 32 + lane];
    float mi = g_macc[n * 32 + lane];
    scat[warp][lane] = xm;
    scat[warp][32 + lane] = mi;
    __syncthreads();

    float acc = cb1[lane];
    #pragma unroll
    for (int k = 0; k < 64; k++) acc += scat[warp][k] * sW1[k * 32 + lane];
    sh[warp][lane] = siluf(acc);
    __syncwarp();

    float acc2 = cb2[lane];
    #pragma unroll
    for (int k = 0; k < 32; k++) acc2 += sh[warp][k] * sW2[k * 32 + lane];
    outx[n * 32 + lane] = siluf(xm + acc2);

    if (lane < 3) {
        float cnt = g_pacc[n * 4 + 3];
        outp[n * 3 + lane] = pos[n * 3 + lane] + g_pacc[n * 4 + lane] / fmaxf(cnt, 1.0f);
    }
}

// ---------------- launch ----------------
extern "C" void kernel_launch(void* const* d_in, const int* in_sizes, int n_in,
                              void* d_out, int out_size) {
    const float* x        = (const float*)d_in[0];
    const int*   ei       = (const int*)d_in[1];
    const float* pos      = (const float*)d_in[2];
    const float* time     = (const float*)d_in[3];
    const int*   batch    = (const int*)d_in[4];
    const float* means    = (const float*)d_in[5];
    const float* betas    = (const float*)d_in[6];
    const float* w_dist   = (const float*)d_in[7];
    const float* msg_w1   = (const float*)d_in[8];
    const float* msg_b1   = (const float*)d_in[9];
    const float* msg_w2   = (const float*)d_in[10];
    const float* msg_b2   = (const float*)d_in[11];
    const float* gate_w   = (const float*)d_in[12];
    const float* gate_b   = (const float*)d_in[13];
    const float* time_w1  = (const float*)d_in[14];
    const float* time_b1  = (const float*)d_in[15];
    const float* time_w2  = (const float*)d_in[16];
    const float* time_b2  = (const float*)d_in[17];
    const float* comb_w1  = (const float*)d_in[18];
    const float* comb_b1  = (const float*)d_in[19];
    const float* comb_w2  = (const float*)d_in[20];
    const float* comb_b2  = (const float*)d_in[21];
    const float* coord_w1 = (const float*)d_in[22];
    const float* coord_b1 = (const float*)d_in[23];
    const float* coord_w2 = (const float*)d_in[24];
    const float* coord_b2 = (const float*)d_in[25];

    float* outx = (float*)d_out;
    float* outp = (float*)d_out + N_NODES * 32;

    k_time<<<G_GRAPHS, 64>>>(time, time_w1, time_b1, time_w2, time_b2);
    k_node<<<N_NODES / 8, 256>>>(x, batch, msg_w1, msg_b1, gate_w, gate_b);
    k_edge<<<E_EDGES / 64, 256>>>(ei, pos, means, betas, w_dist,
                                  msg_w2, msg_b2, coord_w1, coord_b1, coord_w2, coord_b2);
    k_final<<<N_NODES / 8, 256>>>(pos, comb_w1, comb_b1, comb_w2, comb_b2, outx, outp);
}

// round 2
// speedup vs baseline: 1.4089x; 1.4089x over previous
#include <cuda_runtime.h>
#include <math.h>

#define N_NODES 100000
#define E_EDGES 800000
#define G_GRAPHS 512
#define HID 32
#define D_CUT 5.0f
#define TAB 8192

// ---------------- scratch (static, no allocation) ----------------
__device__ __align__(16) float g_ss[G_GRAPHS * 64];   // time MLP output per graph
__device__ __align__(16) float g_xm[N_NODES * 32];    // modulated x
__device__ __align__(16) float g_a[N_NODES * 32];     // x @ msg_w1[:32] + msg_b1
__device__ __align__(16) float g_b[N_NODES * 32];     // x @ msg_w1[32:]
__device__ __align__(16) float g_gate[N_NODES * 32];  // sigmoid(x @ gate_w + gate_b)
__device__ __align__(16) float g_macc[N_NODES * 32];  // segment_sum(m_ij) by j
__device__ __align__(16) float g_pacc[N_NODES * 4];   // pos sums (3) + count (1)
__device__ __align__(16) float g_tab[TAB * 32];       // dist_emb lookup table

__device__ __forceinline__ float siluf(float v) { return v / (1.0f + __expf(-v)); }
__device__ __forceinline__ float sigmf(float v) { return 1.0f / (1.0f + __expf(-v)); }

__device__ __forceinline__ void red_v4(float* p, float a, float b, float c, float d) {
    asm volatile("red.global.add.v4.f32 [%0], {%1,%2,%3,%4};"
                 :: "l"(p), "f"(a), "f"(b), "f"(c), "f"(d) : "memory");
}

// ---------------- K0: build dist_emb table ----------------
// row r: d = r*5/(TAB-1); entry[c] = cutoff(d) * sum_k rbf_k(d) * w_dist[k][c]
__global__ void k_table(const float* __restrict__ means, const float* __restrict__ betas,
                        const float* __restrict__ w_dist) {
    __shared__ float sW[1024];
    __shared__ float sMu[32], sBeta[32];
    int tid = threadIdx.x;
    for (int k = tid; k < 1024; k += 256) sW[k] = w_dist[k];
    if (tid < 32) { sMu[tid] = means[tid]; sBeta[tid] = betas[tid]; }
    __syncthreads();

    int r = blockIdx.x * 8 + (tid >> 5);
    int c = tid & 31;
    float d = (float)r * (D_CUT / (float)(TAB - 1));
    float cutoff = 0.5f * (__cosf(d * (3.14159265358979f / D_CUT)) + 1.0f);
    float ed = __expf(-d);
    float acc = 0.0f;
    #pragma unroll 8
    for (int k = 0; k < 32; k++) {
        float t = ed - sMu[k];
        acc += __expf(-sBeta[k] * t * t) * sW[k * 32 + c];
    }
    g_tab[r * 32 + c] = cutoff * acc;
}

// ---------------- K1: time MLP (G x 128 -> G x 64) ----------------
__global__ void k_time(const float* __restrict__ time,
                       const float* __restrict__ w1, const float* __restrict__ b1,
                       const float* __restrict__ w2, const float* __restrict__ b2) {
    int g = blockIdx.x;
    int t = threadIdx.x; // 64 threads
    __shared__ float trow[128];
    __shared__ float hid[64];
    trow[t]      = time[g * 128 + t];
    trow[t + 64] = time[g * 128 + 64 + t];
    __syncthreads();
    float acc = b1[t];
    #pragma unroll 8
    for (int k = 0; k < 128; k++) acc += trow[k] * w1[k * 64 + t];
    hid[t] = siluf(acc);
    __syncthreads();
    float acc2 = b2[t];
    #pragma unroll 8
    for (int k = 0; k < 64; k++) acc2 += hid[k] * w2[k * 64 + t];
    g_ss[g * 64 + t] = acc2;
}

// ---------------- K2: per-node precompute + accumulator zeroing ----------------
// 256 threads = 64 nodes x 4 lanes; lane owns 8 channels. Three matvecs share
// one input broadcast: per k: 1 shfl + 6 LDS.128 + 24 FFMA.
__global__ void __launch_bounds__(256) k_node(
        const float* __restrict__ x, const int* __restrict__ batch,
        const float* __restrict__ msg_w1, const float* __restrict__ msg_b1,
        const float* __restrict__ gate_w, const float* __restrict__ gate_b) {
    __shared__ __align__(16) float sW1[64 * 32];
    __shared__ __align__(16) float sWg[32 * 32];
    int tid = threadIdx.x;
    for (int k = tid; k < 2048; k += 256) sW1[k] = msg_w1[k];
    for (int k = tid; k < 1024; k += 256) sWg[k] = gate_w[k];
    __syncthreads();

    int sub = tid & 3;
    int c0 = sub * 8;
    int n = blockIdx.x * 64 + (tid >> 2);
    if (n >= N_NODES) return;   // warp-uniform (boundary at warp multiple)

    int bn = batch[n];
    const float4* scp = (const float4*)&g_ss[bn * 64 + c0];
    const float4* shp = (const float4*)&g_ss[bn * 64 + 32 + c0];
    const float4* xp  = (const float4*)&x[n * 32 + c0];
    float4 sc0 = scp[0], sc1 = scp[1];
    float4 sh0 = shp[0], sh1 = shp[1];
    float4 x0 = xp[0], x1 = xp[1];

    float xm[8];
    xm[0] = siluf(x0.x * (1.0f + sc0.x) + sh0.x);
    xm[1] = siluf(x0.y * (1.0f + sc0.y) + sh0.y);
    xm[2] = siluf(x0.z * (1.0f + sc0.z) + sh0.z);
    xm[3] = siluf(x0.w * (1.0f + sc0.w) + sh0.w);
    xm[4] = siluf(x1.x * (1.0f + sc1.x) + sh1.x);
    xm[5] = siluf(x1.y * (1.0f + sc1.y) + sh1.y);
    xm[6] = siluf(x1.z * (1.0f + sc1.z) + sh1.z);
    xm[7] = siluf(x1.w * (1.0f + sc1.w) + sh1.w);

    float a[8], b[8], ga[8];
    #pragma unroll
    for (int u = 0; u < 8; u++) {
        a[u] = msg_b1[c0 + u];
        b[u] = 0.0f;
        ga[u] = gate_b[c0 + u];
    }
    #pragma unroll
    for (int kk = 0; kk < 32; kk++) {
        float v = __shfl_sync(0xffffffffu, xm[kk & 7], kk >> 3, 4);
        const float4* wa = (const float4*)&sW1[kk * 32 + c0];
        const float4* wb = (const float4*)&sW1[(32 + kk) * 32 + c0];
        const float4* wg = (const float4*)&sWg[kk * 32 + c0];
        float4 a0 = wa[0], a1 = wa[1];
        float4 b0 = wb[0], b1v = wb[1];
        float4 g0 = wg[0], g1 = wg[1];
        a[0] += v * a0.x; a[1] += v * a0.y; a[2] += v * a0.z; a[3] += v * a0.w;
        a[4] += v * a1.x; a[5] += v * a1.y; a[6] += v * a1.z; a[7] += v * a1.w;
        b[0] += v * b0.x; b[1] += v * b0.y; b[2] += v * b0.z; b[3] += v * b0.w;
        b[4] += v * b1v.x; b[5] += v * b1v.y; b[6] += v * b1v.z; b[7] += v * b1v.w;
        ga[0] += v * g0.x; ga[1] += v * g0.y; ga[2] += v * g0.z; ga[3] += v * g0.w;
        ga[4] += v * g1.x; ga[5] += v * g1.y; ga[6] += v * g1.z; ga[7] += v * g1.w;
    }

    float4* outxm = (float4*)&g_xm[n * 32 + c0];
    outxm[0] = make_float4(xm[0], xm[1], xm[2], xm[3]);
    outxm[1] = make_float4(xm[4], xm[5], xm[6], xm[7]);
    float4* outa = (float4*)&g_a[n * 32 + c0];
    outa[0] = make_float4(a[0], a[1], a[2], a[3]);
    outa[1] = make_float4(a[4], a[5], a[6], a[7]);
    float4* outb = (float4*)&g_b[n * 32 + c0];
    outb[0] = make_float4(b[0], b[1], b[2], b[3]);
    outb[1] = make_float4(b[4], b[5], b[6], b[7]);
    float4* outg = (float4*)&g_gate[n * 32 + c0];
    outg[0] = make_float4(sigmf(ga[0]), sigmf(ga[1]), sigmf(ga[2]), sigmf(ga[3]));
    outg[1] = make_float4(sigmf(ga[4]), sigmf(ga[5]), sigmf(ga[6]), sigmf(ga[7]));

    float4 z = make_float4(0.f, 0.f, 0.f, 0.f);
    float4* mz = (float4*)&g_macc[n * 32 + c0];
    mz[0] = z; mz[1] = z;
    if (sub == 0) *(float4*)&g_pacc[n * 4] = z;
}

// ---------------- K3: edge kernel ----------------
// 256 threads = 64 edges x 4 lanes; each lane owns 8 channels.
#define MV32(accv, inv, W, c0)                                                   \
    do {                                                                         \
        _Pragma("unroll")                                                        \
        for (int kk = 0; kk < 32; kk++) {                                        \
            float v = __shfl_sync(0xffffffffu, inv[kk & 7], kk >> 3, 4);         \
            const float4* wp = (const float4*)&W[kk * 32 + c0];                  \
            float4 w0 = wp[0];                                                   \
            float4 w1 = wp[1];                                                   \
            accv[0] += v * w0.x; accv[1] += v * w0.y;                            \
            accv[2] += v * w0.z; accv[3] += v * w0.w;                            \
            accv[4] += v * w1.x; accv[5] += v * w1.y;                            \
            accv[6] += v * w1.z; accv[7] += v * w1.w;                            \
        }                                                                        \
    } while (0)

__global__ void __launch_bounds__(256) k_edge(
        const int* __restrict__ ei, const float* __restrict__ pos,
        const float* __restrict__ msg_w2, const float* __restrict__ msg_b2,
        const float* __restrict__ coord_w1, const float* __restrict__ coord_b1,
        const float* __restrict__ coord_w2, const float* __restrict__ coord_b2) {
    __shared__ __align__(16) float sW2[1024];
    __shared__ __align__(16) float sC1[1024];
    __shared__ float sC2[32], sB2[32], sCB1[32];
    __shared__ float sCB2;

    int tid = threadIdx.x;
    for (int k = tid; k < 1024; k += 256) {
        sW2[k] = msg_w2[k];
        sC1[k] = coord_w1[k];
    }
    if (tid < 32) {
        sC2[tid]  = coord_w2[tid];
        sB2[tid]  = msg_b2[tid];
        sCB1[tid] = coord_b1[tid];
    }
    if (tid == 0) sCB2 = coord_b2[0];
    __syncthreads();

    int sub = tid & 3;
    int c0 = sub * 8;
    int e = blockIdx.x * 64 + (tid >> 2); // E = 800000 = 12500*64 exactly

    int i = ei[e];
    int j = ei[E_EDGES + e];

    // gathers (L2-resident)
    const float4* ap = (const float4*)&g_a[i * 32 + c0];
    const float4* bp = (const float4*)&g_b[j * 32 + c0];
    const float4* gp = (const float4*)&g_gate[j * 32 + c0];
    float4 a0 = ap[0], a1 = ap[1];
    float4 b0 = bp[0], b1v = bp[1];
    float4 gq0 = gp[0], gq1 = gp[1];

    float dx = pos[i * 3 + 0] - pos[j * 3 + 0];
    float dy = pos[i * 3 + 1] - pos[j * 3 + 1];
    float dz = pos[i * 3 + 2] - pos[j * 3 + 2];
    float dist = sqrtf(dx * dx + dy * dy + dz * dz);

    // dist_emb via table lookup (includes cutoff*rbf@w_dist); row TAB-1 == 0
    float u = fminf(dist, D_CUT) * ((float)(TAB - 1) / D_CUT);
    int i0 = (int)u;
    i0 = min(i0, TAB - 2);
    float fr = u - (float)i0;
    const float4* r0p = (const float4*)&g_tab[i0 * 32 + c0];
    const float4* r1p = (const float4*)&g_tab[(i0 + 1) * 32 + c0];
    float4 ea0 = r0p[0], ea1 = r0p[1];
    float4 eb0 = r1p[0], eb1 = r1p[1];
    float emb[8];
    emb[0] = ea0.x + fr * (eb0.x - ea0.x);
    emb[1] = ea0.y + fr * (eb0.y - ea0.y);
    emb[2] = ea0.z + fr * (eb0.z - ea0.z);
    emb[3] = ea0.w + fr * (eb0.w - ea0.w);
    emb[4] = ea1.x + fr * (eb1.x - ea1.x);
    emb[5] = ea1.y + fr * (eb1.y - ea1.y);
    emb[6] = ea1.z + fr * (eb1.z - ea1.z);
    emb[7] = ea1.w + fr * (eb1.w - ea1.w);

    // h = silu(a_i + b_j)   (msg_b1 folded into a)
    float h[8];
    h[0] = siluf(a0.x + b0.x);  h[1] = siluf(a0.y + b0.y);
    h[2] = siluf(a0.z + b0.z);  h[3] = siluf(a0.w + b0.w);
    h[4] = siluf(a1.x + b1v.x); h[5] = siluf(a1.y + b1v.y);
    h[6] = siluf(a1.z + b1v.z); h[7] = siluf(a1.w + b1v.w);

    float mm[8];
    #pragma unroll
    for (int w = 0; w < 8; w++) mm[w] = sB2[c0 + w];
    MV32(mm, h, sW2, c0);

    float gv[8] = {gq0.x, gq0.y, gq0.z, gq0.w, gq1.x, gq1.y, gq1.z, gq1.w};
    float m[8];
    #pragma unroll
    for (int w = 0; w < 8; w++) m[w] = siluf(mm[w]) * emb[w] * gv[w];

    float st[8];
    #pragma unroll
    for (int w = 0; w < 8; w++) st[w] = sCB1[c0 + w];
    MV32(st, m, sC1, c0);

    float sp = 0.0f;
    #pragma unroll
    for (int w = 0; w < 8; w++) sp += siluf(st[w]) * sC2[c0 + w];
    sp += __shfl_xor_sync(0xffffffffu, sp, 1);
    sp += __shfl_xor_sync(0xffffffffu, sp, 2);
    float s = sp + sCB2;

    // scatter m_ij into m_acc[j] (two 128-bit vector reductions)
    float* macc = &g_macc[j * 32 + c0];
    red_v4(macc,     m[0], m[1], m[2], m[3]);
    red_v4(macc + 4, m[4], m[5], m[6], m[7]);

    // pos update: one 128-bit vector reduction per edge (lane 0 of the group)
    if (sub == 0) red_v4(&g_pacc[j * 4], dx * s, dy * s, dz * s, 1.0f);
}

// ---------------- K4: combine + outputs ----------------
// 256 threads = 64 nodes x 4 lanes; lane owns 8 output channels.
__global__ void __launch_bounds__(256) k_final(
        const float* __restrict__ pos,
        const float* __restrict__ comb_w1, const float* __restrict__ cb1,
        const float* __restrict__ comb_w2, const float* __restrict__ cb2,
        float* __restrict__ outx, float* __restrict__ outp) {
    __shared__ __align__(16) float sW1[64 * 32];
    __shared__ __align__(16) float sW2[32 * 32];
    int tid = threadIdx.x;
    for (int k = tid; k < 2048; k += 256) sW1[k] = comb_w1[k];
    for (int k = tid; k < 1024; k += 256) sW2[k] = comb_w2[k];
    __syncthreads();

    int sub = tid & 3;
    int c0 = sub * 8;
    int n = blockIdx.x * 64 + (tid >> 2);
    if (n >= N_NODES) return;   // warp-uniform

    // K=64 input: lane sub holds concat(xm, mi)[16*sub .. 16*sub+16)
    const float* src = (sub < 2) ? &g_xm[n * 32] : &g_macc[n * 32];
    const float4* ip = (const float4*)&src[(sub & 1) * 16];
    float4 i0 = ip[0], i1 = ip[1], i2 = ip[2], i3 = ip[3];
    float inv[16] = {i0.x, i0.y, i0.z, i0.w, i1.x, i1.y, i1.z, i1.w,
                     i2.x, i2.y, i2.z, i2.w, i3.x, i3.y, i3.z, i3.w};

    float acc[8];
    #pragma unroll
    for (int w = 0; w < 8; w++) acc[w] = cb1[c0 + w];
    #pragma unroll
    for (int kk = 0; kk < 64; kk++) {
        float v = __shfl_sync(0xffffffffu, inv[kk & 15], kk >> 4, 4);
        const float4* wp = (const float4*)&sW1[kk * 32 + c0];
        float4 w0 = wp[0], w1 = wp[1];
        acc[0] += v * w0.x; acc[1] += v * w0.y; acc[2] += v * w0.z; acc[3] += v * w0.w;
        acc[4] += v * w1.x; acc[5] += v * w1.y; acc[6] += v * w1.z; acc[7] += v * w1.w;
    }
    float hh[8];
    #pragma unroll
    for (int w = 0; w < 8; w++) hh[w] = siluf(acc[w]);

    float acc2[8];
    #pragma unroll
    for (int w = 0; w < 8; w++) acc2[w] = cb2[c0 + w];
    MV32(acc2, hh, sW2, c0);

    const float4* xmp = (const float4*)&g_xm[n * 32 + c0];
    float4 xm0 = xmp[0], xm1 = xmp[1];
    float4 o0, o1;
    o0.x = siluf(xm0.x + acc2[0]); o0.y = siluf(xm0.y + acc2[1]);
    o0.z = siluf(xm0.z + acc2[2]); o0.w = siluf(xm0.w + acc2[3]);
    o1.x = siluf(xm1.x + acc2[4]); o1.y = siluf(xm1.y + acc2[5]);
    o1.z = siluf(xm1.z + acc2[6]); o1.w = siluf(xm1.w + acc2[7]);
    float4* op = (float4*)&outx[n * 32 + c0];
    op[0] = o0; op[1] = o1;

    if (sub == 0) {
        float4 pa = *(const float4*)&g_pacc[n * 4];
        float inv_c = 1.0f / fmaxf(pa.w, 1.0f);
        outp[n * 3 + 0] = pos[n * 3 + 0] + pa.x * inv_c;
        outp[n * 3 + 1] = pos[n * 3 + 1] + pa.y * inv_c;
        outp[n * 3 + 2] = pos[n * 3 + 2] + pa.z * inv_c;
    }
}

// ---------------- launch ----------------
extern "C" void kernel_launch(void* const* d_in, const int* in_sizes, int n_in,
                              void* d_out, int out_size) {
    const float* x        = (const float*)d_in[0];
    const int*   ei       = (const int*)d_in[1];
    const float* pos      = (const float*)d_in[2];
    const float* time     = (const float*)d_in[3];
    const int*   batch    = (const int*)d_in[4];
    const float* means    = (const float*)d_in[5];
    const float* betas    = (const float*)d_in[6];
    const float* w_dist   = (const float*)d_in[7];
    const float* msg_w1   = (const float*)d_in[8];
    const float* msg_b1   = (const float*)d_in[9];
    const float* msg_w2   = (const float*)d_in[10];
    const float* msg_b2   = (const float*)d_in[11];
    const float* gate_w   = (const float*)d_in[12];
    const float* gate_b   = (const float*)d_in[13];
    const float* time_w1  = (const float*)d_in[14];
    const float* time_b1  = (const float*)d_in[15];
    const float* time_w2  = (const float*)d_in[16];
    const float* time_b2  = (const float*)d_in[17];
    const float* comb_w1  = (const float*)d_in[18];
    const float* comb_b1  = (const float*)d_in[19];
    const float* comb_w2  = (const float*)d_in[20];
    const float* comb_b2  = (const float*)d_in[21];
    const float* coord_w1 = (const float*)d_in[22];
    const float* coord_b1 = (const float*)d_in[23];
    const float* coord_w2 = (const float*)d_in[24];
    const float* coord_b2 = (const float*)d_in[25];

    float* outx = (float*)d_out;
    float* outp = (float*)d_out + N_NODES * 32;

    k_table<<<TAB / 8, 256>>>(means, betas, w_dist);
    k_time<<<G_GRAPHS, 64>>>(time, time_w1, time_b1, time_w2, time_b2);
    k_node<<<(N_NODES + 63) / 64, 256>>>(x, batch, msg_w1, msg_b1, gate_w, gate_b);
    k_edge<<<E_EDGES / 64, 256>>>(ei, pos, msg_w2, msg_b2,
                                  coord_w1, coord_b1, coord_w2, coord_b2);
    k_final<<<(N_NODES + 63) / 64, 256>>>(pos, comb_w1, comb_b1, comb_w2, comb_b2,
                                          outx, outp);
}

// round 3
// speedup vs baseline: 1.6106x; 1.1432x over previous
#include <cuda_runtime.h>
#include <math.h>

#define N_NODES 100000
#define E_EDGES 800000
#define G_GRAPHS 512
#define HID 32
#define D_CUT 5.0f
#define TAB 8192

// ---------------- scratch (static, no allocation) ----------------
__device__ __align__(16) float g_ss[G_GRAPHS * 64];   // time MLP output per graph
__device__ __align__(16) float g_xm[N_NODES * 32];    // modulated x
__device__ __align__(16) float g_a[N_NODES * 32];     // x @ msg_w1[:32] + msg_b1
__device__ __align__(16) float g_b[N_NODES * 32];     // x @ msg_w1[32:]
__device__ __align__(16) float g_gate[N_NODES * 32];  // sigmoid(x @ gate_w + gate_b)
__device__ __align__(16) float g_macc[N_NODES * 32];  // segment_sum(m_ij) by j
__device__ __align__(16) float g_pacc[N_NODES * 4];   // pos sums (3) + count (1)
__device__ __align__(16) float4 g_pos4[N_NODES];      // padded positions
__device__ __align__(16) float g_tab[TAB * 32];       // dist_emb lookup table

__device__ __forceinline__ float siluf(float v) { return v / (1.0f + __expf(-v)); }
__device__ __forceinline__ float sigmf(float v) { return 1.0f / (1.0f + __expf(-v)); }

__device__ __forceinline__ void red_v4(float* p, float a, float b, float c, float d) {
    asm volatile("red.global.add.v4.f32 [%0], {%1,%2,%3,%4};"
                 :: "l"(p), "f"(a), "f"(b), "f"(c), "f"(d) : "memory");
}

// ---------------- K0: build dist_emb table ----------------
__global__ void k_table(const float* __restrict__ means, const float* __restrict__ betas,
                        const float* __restrict__ w_dist) {
    __shared__ float sW[1024];
    __shared__ float sMu[32], sBeta[32];
    int tid = threadIdx.x;
    for (int k = tid; k < 1024; k += 256) sW[k] = w_dist[k];
    if (tid < 32) { sMu[tid] = means[tid]; sBeta[tid] = betas[tid]; }
    __syncthreads();

    int r = blockIdx.x * 8 + (tid >> 5);
    int c = tid & 31;
    float d = (float)r * (D_CUT / (float)(TAB - 1));
    float cutoff = 0.5f * (__cosf(d * (3.14159265358979f / D_CUT)) + 1.0f);
    float ed = __expf(-d);
    float acc = 0.0f;
    #pragma unroll 8
    for (int k = 0; k < 32; k++) {
        float t = ed - sMu[k];
        acc += __expf(-sBeta[k] * t * t) * sW[k * 32 + c];
    }
    g_tab[r * 32 + c] = cutoff * acc;
}

// ---------------- K1: time MLP (G x 128 -> G x 64) ----------------
__global__ void k_time(const float* __restrict__ time,
                       const float* __restrict__ w1, const float* __restrict__ b1,
                       const float* __restrict__ w2, const float* __restrict__ b2) {
    int g = blockIdx.x;
    int t = threadIdx.x; // 64 threads
    __shared__ float trow[128];
    __shared__ float hid[64];
    trow[t]      = time[g * 128 + t];
    trow[t + 64] = time[g * 128 + 64 + t];
    __syncthreads();
    float acc = b1[t];
    #pragma unroll 8
    for (int k = 0; k < 128; k++) acc += trow[k] * w1[k * 64 + t];
    hid[t] = siluf(acc);
    __syncthreads();
    float acc2 = b2[t];
    #pragma unroll 8
    for (int k = 0; k < 64; k++) acc2 += hid[k] * w2[k * 64 + t];
    g_ss[g * 64 + t] = acc2;
}

// ---------------- K2: per-node precompute + accumulator zeroing ----------------
__global__ void __launch_bounds__(256) k_node(
        const float* __restrict__ x, const int* __restrict__ batch,
        const float* __restrict__ pos,
        const float* __restrict__ msg_w1, const float* __restrict__ msg_b1,
        const float* __restrict__ gate_w, const float* __restrict__ gate_b) {
    __shared__ __align__(16) float sW1[64 * 32];
    __shared__ __align__(16) float sWg[32 * 32];
    int tid = threadIdx.x;
    for (int k = tid; k < 2048; k += 256) sW1[k] = msg_w1[k];
    for (int k = tid; k < 1024; k += 256) sWg[k] = gate_w[k];
    __syncthreads();

    int sub = tid & 3;
    int c0 = sub * 8;
    int n = blockIdx.x * 64 + (tid >> 2);
    if (n >= N_NODES) return;   // warp-uniform (boundary at warp multiple)

    int bn = batch[n];
    const float4* scp = (const float4*)&g_ss[bn * 64 + c0];
    const float4* shp = (const float4*)&g_ss[bn * 64 + 32 + c0];
    const float4* xp  = (const float4*)&x[n * 32 + c0];
    float4 sc0 = scp[0], sc1 = scp[1];
    float4 sh0 = shp[0], sh1 = shp[1];
    float4 x0 = xp[0], x1 = xp[1];

    float xm[8];
    xm[0] = siluf(x0.x * (1.0f + sc0.x) + sh0.x);
    xm[1] = siluf(x0.y * (1.0f + sc0.y) + sh0.y);
    xm[2] = siluf(x0.z * (1.0f + sc0.z) + sh0.z);
    xm[3] = siluf(x0.w * (1.0f + sc0.w) + sh0.w);
    xm[4] = siluf(x1.x * (1.0f + sc1.x) + sh1.x);
    xm[5] = siluf(x1.y * (1.0f + sc1.y) + sh1.y);
    xm[6] = siluf(x1.z * (1.0f + sc1.z) + sh1.z);
    xm[7] = siluf(x1.w * (1.0f + sc1.w) + sh1.w);

    float a[8], b[8], ga[8];
    #pragma unroll
    for (int u = 0; u < 8; u++) {
        a[u] = msg_b1[c0 + u];
        b[u] = 0.0f;
        ga[u] = gate_b[c0 + u];
    }
    #pragma unroll
    for (int kk = 0; kk < 32; kk++) {
        float v = __shfl_sync(0xffffffffu, xm[kk & 7], kk >> 3, 4);
        const float4* wa = (const float4*)&sW1[kk * 32 + c0];
        const float4* wb = (const float4*)&sW1[(32 + kk) * 32 + c0];
        const float4* wg = (const float4*)&sWg[kk * 32 + c0];
        float4 a0 = wa[0], a1 = wa[1];
        float4 b0 = wb[0], b1v = wb[1];
        float4 g0 = wg[0], g1 = wg[1];
        a[0] += v * a0.x; a[1] += v * a0.y; a[2] += v * a0.z; a[3] += v * a0.w;
        a[4] += v * a1.x; a[5] += v * a1.y; a[6] += v * a1.z; a[7] += v * a1.w;
        b[0] += v * b0.x; b[1] += v * b0.y; b[2] += v * b0.z; b[3] += v * b0.w;
        b[4] += v * b1v.x; b[5] += v * b1v.y; b[6] += v * b1v.z; b[7] += v * b1v.w;
        ga[0] += v * g0.x; ga[1] += v * g0.y; ga[2] += v * g0.z; ga[3] += v * g0.w;
        ga[4] += v * g1.x; ga[5] += v * g1.y; ga[6] += v * g1.z; ga[7] += v * g1.w;
    }

    float4* outxm = (float4*)&g_xm[n * 32 + c0];
    outxm[0] = make_float4(xm[0], xm[1], xm[2], xm[3]);
    outxm[1] = make_float4(xm[4], xm[5], xm[6], xm[7]);
    float4* outa = (float4*)&g_a[n * 32 + c0];
    outa[0] = make_float4(a[0], a[1], a[2], a[3]);
    outa[1] = make_float4(a[4], a[5], a[6], a[7]);
    float4* outb = (float4*)&g_b[n * 32 + c0];
    outb[0] = make_float4(b[0], b[1], b[2], b[3]);
    outb[1] = make_float4(b[4], b[5], b[6], b[7]);
    float4* outg = (float4*)&g_gate[n * 32 + c0];
    outg[0] = make_float4(sigmf(ga[0]), sigmf(ga[1]), sigmf(ga[2]), sigmf(ga[3]));
    outg[1] = make_float4(sigmf(ga[4]), sigmf(ga[5]), sigmf(ga[6]), sigmf(ga[7]));

    float4 z = make_float4(0.f, 0.f, 0.f, 0.f);
    float4* mz = (float4*)&g_macc[n * 32 + c0];
    mz[0] = z; mz[1] = z;
    if (sub == 0) {
        *(float4*)&g_pacc[n * 4] = z;
        g_pos4[n] = make_float4(pos[n * 3], pos[n * 3 + 1], pos[n * 3 + 2], 0.0f);
    }
}

// ---------------- K3: edge kernel (NE=2 per 4-lane group) ----------------
// 256 threads = 64 groups x 4 lanes; each group handles 2 adjacent edges;
// each lane owns 8 channels. Weight float4s loaded once per k, used for both
// edges -> LDS instructions per edge halved vs NE=1.
#define MV32X2(accA, accB, inA, inB, W, c0)                                      \
    do {                                                                         \
        _Pragma("unroll")                                                        \
        for (int kk = 0; kk < 32; kk++) {                                        \
            float vA = __shfl_sync(0xffffffffu, inA[kk & 7], kk >> 3, 4);        \
            float vB = __shfl_sync(0xffffffffu, inB[kk & 7], kk >> 3, 4);        \
            const float4* wp = (const float4*)&W[kk * 32 + c0];                  \
            float4 w0 = wp[0];                                                   \
            float4 w1 = wp[1];                                                   \
            accA[0] += vA * w0.x; accA[1] += vA * w0.y;                          \
            accA[2] += vA * w0.z; accA[3] += vA * w0.w;                          \
            accA[4] += vA * w1.x; accA[5] += vA * w1.y;                          \
            accA[6] += vA * w1.z; accA[7] += vA * w1.w;                          \
            accB[0] += vB * w0.x; accB[1] += vB * w0.y;                          \
            accB[2] += vB * w0.z; accB[3] += vB * w0.w;                          \
            accB[4] += vB * w1.x; accB[5] += vB * w1.y;                          \
            accB[6] += vB * w1.z; accB[7] += vB * w1.w;                          \
        }                                                                        \
    } while (0)

__global__ void __launch_bounds__(256) k_edge(
        const int* __restrict__ ei,
        const float* __restrict__ msg_w2, const float* __restrict__ msg_b2,
        const float* __restrict__ coord_w1, const float* __restrict__ coord_b1,
        const float* __restrict__ coord_w2, const float* __restrict__ coord_b2) {
    __shared__ __align__(16) float sW2[1024];
    __shared__ __align__(16) float sC1[1024];
    __shared__ float sC2[32], sB2[32], sCB1[32];
    __shared__ float sCB2;

    int tid = threadIdx.x;
    for (int k = tid; k < 1024; k += 256) {
        sW2[k] = msg_w2[k];
        sC1[k] = coord_w1[k];
    }
    if (tid < 32) {
        sC2[tid]  = coord_w2[tid];
        sB2[tid]  = msg_b2[tid];
        sCB1[tid] = coord_b1[tid];
    }
    if (tid == 0) sCB2 = coord_b2[0];
    __syncthreads();

    int sub = tid & 3;
    int c0 = sub * 8;
    int e0 = blockIdx.x * 128 + (tid >> 2) * 2; // E = 800000 = 6250*128 exactly

    int2 ip = *(const int2*)&ei[e0];
    int2 jp = *(const int2*)&ei[E_EDGES + e0];
    int iA = ip.x, iB = ip.y;
    int jA = jp.x, jB = jp.y;

    // positions (padded float4, broadcast within group)
    float4 piA = g_pos4[iA], pjA = g_pos4[jA];
    float4 piB = g_pos4[iB], pjB = g_pos4[jB];
    float dxA = piA.x - pjA.x, dyA = piA.y - pjA.y, dzA = piA.z - pjA.z;
    float dxB = piB.x - pjB.x, dyB = piB.y - pjB.y, dzB = piB.z - pjB.z;
    float distA = sqrtf(dxA * dxA + dyA * dyA + dzA * dzA);
    float distB = sqrtf(dxB * dxB + dyB * dyB + dzB * dzB);

    // dist_emb via table lookup + lerp, fused with gate -> eg = emb * gate
    float uA = fminf(distA, D_CUT) * ((float)(TAB - 1) / D_CUT);
    float uB = fminf(distB, D_CUT) * ((float)(TAB - 1) / D_CUT);
    int i0A = min((int)uA, TAB - 2);
    int i0B = min((int)uB, TAB - 2);
    float frA = uA - (float)i0A;
    float frB = uB - (float)i0B;

    const float4* tA0 = (const float4*)&g_tab[i0A * 32 + c0];
    const float4* tA1 = (const float4*)&g_tab[(i0A + 1) * 32 + c0];
    const float4* tB0 = (const float4*)&g_tab[i0B * 32 + c0];
    const float4* tB1 = (const float4*)&g_tab[(i0B + 1) * 32 + c0];
    const float4* gAp = (const float4*)&g_gate[jA * 32 + c0];
    const float4* gBp = (const float4*)&g_gate[jB * 32 + c0];

    float egA[8], egB[8];
    {
        float4 a0 = tA0[0], a1 = tA0[1], b0 = tA1[0], b1 = tA1[1];
        float4 g0 = gAp[0], g1 = gAp[1];
        egA[0] = (a0.x + frA * (b0.x - a0.x)) * g0.x;
        egA[1] = (a0.y + frA * (b0.y - a0.y)) * g0.y;
        egA[2] = (a0.z + frA * (b0.z - a0.z)) * g0.z;
        egA[3] = (a0.w + frA * (b0.w - a0.w)) * g0.w;
        egA[4] = (a1.x + frA * (b1.x - a1.x)) * g1.x;
        egA[5] = (a1.y + frA * (b1.y - a1.y)) * g1.y;
        egA[6] = (a1.z + frA * (b1.z - a1.z)) * g1.z;
        egA[7] = (a1.w + frA * (b1.w - a1.w)) * g1.w;
    }
    {
        float4 a0 = tB0[0], a1 = tB0[1], b0 = tB1[0], b1 = tB1[1];
        float4 g0 = gBp[0], g1 = gBp[1];
        egB[0] = (a0.x + frB * (b0.x - a0.x)) * g0.x;
        egB[1] = (a0.y + frB * (b0.y - a0.y)) * g0.y;
        egB[2] = (a0.z + frB * (b0.z - a0.z)) * g0.z;
        egB[3] = (a0.w + frB * (b0.w - a0.w)) * g0.w;
        egB[4] = (a1.x + frB * (b1.x - a1.x)) * g1.x;
        egB[5] = (a1.y + frB * (b1.y - a1.y)) * g1.y;
        egB[6] = (a1.z + frB * (b1.z - a1.z)) * g1.z;
        egB[7] = (a1.w + frB * (b1.w - a1.w)) * g1.w;
    }

    // h = silu(a_i + b_j)
    float hA[8], hB[8];
    {
        const float4* ap = (const float4*)&g_a[iA * 32 + c0];
        const float4* bp = (const float4*)&g_b[jA * 32 + c0];
        float4 a0 = ap[0], a1 = ap[1], b0 = bp[0], b1 = bp[1];
        hA[0] = siluf(a0.x + b0.x); hA[1] = siluf(a0.y + b0.y);
        hA[2] = siluf(a0.z + b0.z); hA[3] = siluf(a0.w + b0.w);
        hA[4] = siluf(a1.x + b1.x); hA[5] = siluf(a1.y + b1.y);
        hA[6] = siluf(a1.z + b1.z); hA[7] = siluf(a1.w + b1.w);
    }
    {
        const float4* ap = (const float4*)&g_a[iB * 32 + c0];
        const float4* bp = (const float4*)&g_b[jB * 32 + c0];
        float4 a0 = ap[0], a1 = ap[1], b0 = bp[0], b1 = bp[1];
        hB[0] = siluf(a0.x + b0.x); hB[1] = siluf(a0.y + b0.y);
        hB[2] = siluf(a0.z + b0.z); hB[3] = siluf(a0.w + b0.w);
        hB[4] = siluf(a1.x + b1.x); hB[5] = siluf(a1.y + b1.y);
        hB[6] = siluf(a1.z + b1.z); hB[7] = siluf(a1.w + b1.w);
    }

    float mmA[8], mmB[8];
    #pragma unroll
    for (int u = 0; u < 8; u++) { mmA[u] = sB2[c0 + u]; mmB[u] = sB2[c0 + u]; }
    MV32X2(mmA, mmB, hA, hB, sW2, c0);

    float mA[8], mB[8];
    #pragma unroll
    for (int u = 0; u < 8; u++) {
        mA[u] = siluf(mmA[u]) * egA[u];
        mB[u] = siluf(mmB[u]) * egB[u];
    }

    // scatter m_ij early (retire atomics while MV2 runs)
    float* maccA = &g_macc[jA * 32 + c0];
    red_v4(maccA,     mA[0], mA[1], mA[2], mA[3]);
    red_v4(maccA + 4, mA[4], mA[5], mA[6], mA[7]);
    float* maccB = &g_macc[jB * 32 + c0];
    red_v4(maccB,     mB[0], mB[1], mB[2], mB[3]);
    red_v4(maccB + 4, mB[4], mB[5], mB[6], mB[7]);

    float stA[8], stB[8];
    #pragma unroll
    for (int u = 0; u < 8; u++) { stA[u] = sCB1[c0 + u]; stB[u] = sCB1[c0 + u]; }
    MV32X2(stA, stB, mA, mB, sC1, c0);

    float spA = 0.0f, spB = 0.0f;
    #pragma unroll
    for (int u = 0; u < 8; u++) {
        float w = sC2[c0 + u];
        spA += siluf(stA[u]) * w;
        spB += siluf(stB[u]) * w;
    }
    spA += __shfl_xor_sync(0xffffffffu, spA, 1);
    spA += __shfl_xor_sync(0xffffffffu, spA, 2);
    spB += __shfl_xor_sync(0xffffffffu, spB, 1);
    spB += __shfl_xor_sync(0xffffffffu, spB, 2);
    float sA = spA + sCB2;
    float sB = spB + sCB2;

    if (sub == 0) {
        red_v4(&g_pacc[jA * 4], dxA * sA, dyA * sA, dzA * sA, 1.0f);
        red_v4(&g_pacc[jB * 4], dxB * sB, dyB * sB, dzB * sB, 1.0f);
    }
}

// ---------------- K4: combine + outputs ----------------
#define MV32(accv, inv, W, c0)                                                   \
    do {                                                                         \
        _Pragma("unroll")                                                        \
        for (int kk = 0; kk < 32; kk++) {                                        \
            float v = __shfl_sync(0xffffffffu, inv[kk & 7], kk >> 3, 4);         \
            const float4* wp = (const float4*)&W[kk * 32 + c0];                  \
            float4 w0 = wp[0];                                                   \
            float4 w1 = wp[1];                                                   \
            accv[0] += v * w0.x; accv[1] += v * w0.y;                            \
            accv[2] += v * w0.z; accv[3] += v * w0.w;                            \
            accv[4] += v * w1.x; accv[5] += v * w1.y;                            \
            accv[6] += v * w1.z; accv[7] += v * w1.w;                            \
        }                                                                        \
    } while (0)

__global__ void __launch_bounds__(256) k_final(
        const float* __restrict__ pos,
        const float* __restrict__ comb_w1, const float* __restrict__ cb1,
        const float* __restrict__ comb_w2, const float* __restrict__ cb2,
        float* __restrict__ outx, float* __restrict__ outp) {
    __shared__ __align__(16) float sW1[64 * 32];
    __shared__ __align__(16) float sW2[32 * 32];
    int tid = threadIdx.x;
    for (int k = tid; k < 2048; k += 256) sW1[k] = comb_w1[k];
    for (int k = tid; k < 1024; k += 256) sW2[k] = comb_w2[k];
    __syncthreads();

    int sub = tid & 3;
    int c0 = sub * 8;
    int n = blockIdx.x * 64 + (tid >> 2);
    if (n >= N_NODES) return;   // warp-uniform

    const float* src = (sub < 2) ? &g_xm[n * 32] : &g_macc[n * 32];
    const float4* ip = (const float4*)&src[(sub & 1) * 16];
    float4 i0 = ip[0], i1 = ip[1], i2 = ip[2], i3 = ip[3];
    float inv[16] = {i0.x, i0.y, i0.z, i0.w, i1.x, i1.y, i1.z, i1.w,
                     i2.x, i2.y, i2.z, i2.w, i3.x, i3.y, i3.z, i3.w};

    float acc[8];
    #pragma unroll
    for (int w = 0; w < 8; w++) acc[w] = cb1[c0 + w];
    #pragma unroll
    for (int kk = 0; kk < 64; kk++) {
        float v = __shfl_sync(0xffffffffu, inv[kk & 15], kk >> 4, 4);
        const float4* wp = (const float4*)&sW1[kk * 32 + c0];
        float4 w0 = wp[0], w1 = wp[1];
        acc[0] += v * w0.x; acc[1] += v * w0.y; acc[2] += v * w0.z; acc[3] += v * w0.w;
        acc[4] += v * w1.x; acc[5] += v * w1.y; acc[6] += v * w1.z; acc[7] += v * w1.w;
    }
    float hh[8];
    #pragma unroll
    for (int w = 0; w < 8; w++) hh[w] = siluf(acc[w]);

    float acc2[8];
    #pragma unroll
    for (int w = 0; w < 8; w++) acc2[w] = cb2[c0 + w];
    MV32(acc2, hh, sW2, c0);

    const float4* xmp = (const float4*)&g_xm[n * 32 + c0];
    float4 xm0 = xmp[0], xm1 = xmp[1];
    float4 o0, o1;
    o0.x = siluf(xm0.x + acc2[0]); o0.y = siluf(xm0.y + acc2[1]);
    o0.z = siluf(xm0.z + acc2[2]); o0.w = siluf(xm0.w + acc2[3]);
    o1.x = siluf(xm1.x + acc2[4]); o1.y = siluf(xm1.y + acc2[5]);
    o1.z = siluf(xm1.z + acc2[6]); o1.w = siluf(xm1.w + acc2[7]);
    float4* op = (float4*)&outx[n * 32 + c0];
    op[0] = o0; op[1] = o1;

    if (sub == 0) {
        float4 pa = *(const float4*)&g_pacc[n * 4];
        float inv_c = 1.0f / fmaxf(pa.w, 1.0f);
        outp[n * 3 + 0] = pos[n * 3 + 0] + pa.x * inv_c;
        outp[n * 3 + 1] = pos[n * 3 + 1] + pa.y * inv_c;
        outp[n * 3 + 2] = pos[n * 3 + 2] + pa.z * inv_c;
    }
}

// ---------------- launch ----------------
extern "C" void kernel_launch(void* const* d_in, const int* in_sizes, int n_in,
                              void* d_out, int out_size) {
    const float* x        = (const float*)d_in[0];
    const int*   ei       = (const int*)d_in[1];
    const float* pos      = (const float*)d_in[2];
    const float* time     = (const float*)d_in[3];
    const int*   batch    = (const int*)d_in[4];
    const float* means    = (const float*)d_in[5];
    const float* betas    = (const float*)d_in[6];
    const float* w_dist   = (const float*)d_in[7];
    const float* msg_w1   = (const float*)d_in[8];
    const float* msg_b1   = (const float*)d_in[9];
    const float* msg_w2   = (const float*)d_in[10];
    const float* msg_b2   = (const float*)d_in[11];
    const float* gate_w   = (const float*)d_in[12];
    const float* gate_b   = (const float*)d_in[13];
    const float* time_w1  = (const float*)d_in[14];
    const float* time_b1  = (const float*)d_in[15];
    const float* time_w2  = (const float*)d_in[16];
    const float* time_b2  = (const float*)d_in[17];
    const float* comb_w1  = (const float*)d_in[18];
    const float* comb_b1  = (const float*)d_in[19];
    const float* comb_w2  = (const float*)d_in[20];
    const float* comb_b2  = (const float*)d_in[21];
    const float* coord_w1 = (const float*)d_in[22];
    const float* coord_b1 = (const float*)d_in[23];
    const float* coord_w2 = (const float*)d_in[24];
    const float* coord_b2 = (const float*)d_in[25];

    float* outx = (float*)d_out;
    float* outp = (float*)d_out + N_NODES * 32;

    k_table<<<TAB / 8, 256>>>(means, betas, w_dist);
    k_time<<<G_GRAPHS, 64>>>(time, time_w1, time_b1, time_w2, time_b2);
    k_node<<<(N_NODES + 63) / 64, 256>>>(x, batch, pos, msg_w1, msg_b1, gate_w, gate_b);
    k_edge<<<E_EDGES / 128, 256>>>(ei, msg_w2, msg_b2,
                                   coord_w1, coord_b1, coord_w2, coord_b2);
    k_final<<<(N_NODES + 63) / 64, 256>>>(pos, comb_w1, comb_b1, comb_w2, comb_b2,
                                          outx, outp);
}